// round 11
// baseline (speedup 1.0000x reference)
#include <cuda_runtime.h>
#include <cuda_bf16.h>
#include <cstddef>

// Problem constants
#define BB 8
#define TT 16
#define HH 64
#define WW 64
#define CIN 32
#define FF 32
#define G4F 128
#define BN_EPS 1e-3f

// ===================== xg kernel geometry (R10, measured 805us) ============
#define TW 32
#define TH 16
#define IN_ROWS 18
#define IN_COLS 34
#define ROW_STRIDE (32 * IN_COLS)
#define SIN_FLOATS (IN_ROWS * ROW_STRIDE)     // 19584
#define SWBUF_FLOATS (2 * 32 * 32)            // 2048
#define XG_SMEM ((SIN_FLOATS + SWBUF_FLOATS) * 4)  // 86528 -> 2 CTA/SM

// ===================== lstm task geometry ==================================
// task = 32 wide x 8 tall x 32 gate-channels; 512 tasks/step
#define LTH 8
#define LIN_ROWS 10
#define LSIN_FLOATS (LIN_ROWS * ROW_STRIDE)   // 10880
#define LS_SMEM ((LSIN_FLOATS + SWBUF_FLOATS + 16) * 4)  // 51776 -> 4 CTA/SM
#define LSTM_GRID 592                          // 148 SMs x 4 CTAs, all resident
#define NTASKS 512

// ======================= device scratch (no allocs) ========================
__device__ float g_xg[(size_t)BB * TT * HH * WW * G4F];
// h state TRANSPOSED: [2][b][f][y][x]
__device__ float g_h[2][(size_t)BB * FF * HH * WW];
__device__ float g_c[(size_t)BB * HH * WW * FF];
__device__ unsigned g_bar[TT];
__device__ unsigned g_task[TT];

// ======================= helpers ===========================================
__device__ __forceinline__ float hsig(float x) {
    return __saturatef(fmaf(0.2f, x, 0.5f));
}
__device__ __forceinline__ unsigned long long pack2(float v) {
    unsigned long long r;
    asm("mov.b64 %0, {%1, %1};" : "=l"(r) : "f"(v));
    return r;
}
__device__ __forceinline__ void ffma2(unsigned long long& d,
                                      unsigned long long a,
                                      unsigned long long b) {
    asm("fma.rn.f32x2 %0, %1, %2, %3;" : "=l"(d) : "l"(a), "l"(b), "l"(d));
}
__device__ __forceinline__ void unpack2(unsigned long long p, float& lo, float& hi) {
    asm("mov.b64 {%0, %1}, %2;" : "=f"(lo), "=f"(hi) : "l"(p));
}

// One 3x3 tap over 32 cin for 2 pixels (row offset ROWOFF), 32 couts.
template <int ROWOFF>
__device__ __forceinline__ void conv_tap_t(
    const float* __restrict__ s_in, const float* __restrict__ wb,
    int pr, int px, int dy, int dx,
    unsigned long long* acc0, unsigned long long* acc1)
{
    const float* i0 = &s_in[(pr + dy) * ROW_STRIDE + (px + dx)];
    const float* i1 = i0 + ROWOFF * ROW_STRIDE;
#pragma unroll 4
    for (int cin = 0; cin < 32; cin++) {
        unsigned long long v0 = pack2(i0[cin * IN_COLS]);
        unsigned long long v1 = pack2(i1[cin * IN_COLS]);
        const ulonglong2* w2 = (const ulonglong2*)(wb + cin * 32);
#pragma unroll
        for (int q = 0; q < 8; q++) {
            ulonglong2 w = w2[q];
            ffma2(acc0[q * 2 + 0], v0, w.x);
            ffma2(acc0[q * 2 + 1], v0, w.y);
            ffma2(acc1[q * 2 + 0], v1, w.x);
            ffma2(acc1[q * 2 + 1], v1, w.y);
        }
    }
}

// ---- weight tap loaders ----
__device__ __forceinline__ void load_tap_xg(
    float* __restrict__ dst, const float* __restrict__ Wx, int kk, int cc, int tid)
{
    int cin = tid >> 3, col0 = (tid & 7) * 4;
    float4 w = *(const float4*)&Wx[((size_t)(kk * CIN + cin)) * G4F + cc * 32 + col0];
    *(float4*)&dst[cin * 32 + col0] = w;
}
// 128-thread variant: 2 float4 per thread, gate-interleaved cols.
__device__ __forceinline__ void load_tap_lstm128(
    float* __restrict__ dst, const float* __restrict__ Wh, int kk, int fc, int tid)
{
    int cin = tid >> 2, col0 = (tid & 3) * 8;
    int cout0 = (col0 >> 3) * 32 + fc * 8;
    const float* src = &Wh[((size_t)(kk * CIN + cin)) * G4F + cout0];
    *(float4*)&dst[cin * 32 + col0]     = *(const float4*)&src[0];
    *(float4*)&dst[cin * 32 + col0 + 4] = *(const float4*)&src[4];
}

// x tile loader (R10): [y][x][cin] gmem, float4 along cin.
__device__ __forceinline__ void load_x_tile(
    float* __restrict__ s_in, const float* __restrict__ src,
    int ty0, int tx0, int tid)
{
    for (int j = tid; j < 612 * 8; j += 256) {
        int c4 = j & 7;
        int p  = j >> 3;
        int row = p / IN_COLS, col = p - row * IN_COLS;
        int gy = ty0 + row - 1, gx = tx0 + col - 1;
        float4 v = make_float4(0.f, 0.f, 0.f, 0.f);
        if ((unsigned)gy < (unsigned)HH && (unsigned)gx < (unsigned)WW)
            v = __ldg((const float4*)&src[((size_t)gy * WW + gx) * CIN + c4 * 4]);
        float* d = &s_in[(row * 32 + c4 * 4) * IN_COLS + col];
        d[0 * IN_COLS] = v.x;
        d[1 * IN_COLS] = v.y;
        d[2 * IN_COLS] = v.z;
        d[3 * IN_COLS] = v.w;
    }
}

// h tile loader (10 rows, transposed [f][y][x] layout, 128 threads).
__device__ __forceinline__ void load_h_tile10(
    float* __restrict__ s_in, const float* __restrict__ src,
    int ty0, int tx0, int tid)
{
    for (int j = tid; j < LIN_ROWS * 32 * 8; j += 128) {
        int c4  = j & 7;
        int cin = (j >> 3) & 31;
        int row = j >> 8;              // 0..9
        int gy = ty0 + row - 1;
        int gx0 = tx0 + c4 * 4;
        float4 v = make_float4(0.f, 0.f, 0.f, 0.f);
        if ((unsigned)gy < (unsigned)HH)
            v = __ldcv((const float4*)&src[((size_t)cin * HH + gy) * WW + gx0]);
        float* d = &s_in[(row * 32 + cin) * IN_COLS + (c4 * 4 + 1)];
        d[0] = v.x; d[1] = v.y; d[2] = v.z; d[3] = v.w;
    }
    for (int j = tid; j < LIN_ROWS * 32 * 2; j += 128) {
        int e   = j & 1;
        int cin = (j >> 1) & 31;
        int row = j >> 6;              // 0..9
        int gy = ty0 + row - 1;
        int gx = e ? (tx0 + 32) : (tx0 - 1);
        float v = 0.f;
        if ((unsigned)gy < (unsigned)HH && (unsigned)gx < (unsigned)WW)
            v = __ldcv(&src[((size_t)cin * HH + gy) * WW + gx]);
        s_in[(row * 32 + cin) * IN_COLS + (e ? 33 : 0)] = v;
    }
}

// ---------------------------------------------------------------------------
// Kernel 1: xg = conv(x, Wx) + b (R10 config, unchanged). grid (8,4,128).
// ---------------------------------------------------------------------------
__global__ void __launch_bounds__(256, 2) xg_conv_kernel(
    const float* __restrict__ x, const float* __restrict__ Wx,
    const float* __restrict__ b)
{
    extern __shared__ float sm[];
    float* s_in = sm;
    float* s_w  = sm + SIN_FLOATS;

    const int tile = blockIdx.x;
    const int cc   = blockIdx.y;
    const int n    = blockIdx.z;
    const int tx0 = (tile & 1) * TW;
    const int ty0 = (tile >> 1) * TH;
    const int tid = threadIdx.x;

    load_x_tile(s_in, x + (size_t)n * HH * WW * CIN, ty0, tx0, tid);
    load_tap_xg(s_w, Wx, 0, cc, tid);
    __syncthreads();

    const int px = tid & 31, pr = tid >> 5;
    unsigned long long acc0[16], acc1[16];
#pragma unroll
    for (int m = 0; m < 16; m++) { acc0[m] = 0ull; acc1[m] = 0ull; }

#pragma unroll
    for (int tap = 0; tap < 9; tap++) {
        if (tap < 8)
            load_tap_xg(&s_w[((tap + 1) & 1) * 1024], Wx, tap + 1, cc, tid);
        conv_tap_t<8>(s_in, &s_w[(tap & 1) * 1024], pr, px, tap / 3, tap % 3,
                      acc0, acc1);
        __syncthreads();
    }

    float a0[32], a1[32];
#pragma unroll
    for (int m = 0; m < 16; m++) {
        unpack2(acc0[m], a0[2 * m], a0[2 * m + 1]);
        unpack2(acc1[m], a1[2 * m], a1[2 * m + 1]);
    }

    const int gx = tx0 + px;
    const int gy0 = ty0 + pr, gy1 = gy0 + 8;
    float* o0 = &g_xg[(((size_t)n * HH + gy0) * WW + gx) * G4F + cc * 32];
    float* o1 = &g_xg[(((size_t)n * HH + gy1) * WW + gx) * G4F + cc * 32];
#pragma unroll
    for (int q = 0; q < 8; q++) {
        float4 bv = *(const float4*)&b[cc * 32 + q * 4];
        ((float4*)o0)[q] = make_float4(a0[q*4+0]+bv.x, a0[q*4+1]+bv.y,
                                       a0[q*4+2]+bv.z, a0[q*4+3]+bv.w);
        ((float4*)o1)[q] = make_float4(a1[q*4+0]+bv.x, a1[q*4+1]+bv.y,
                                       a1[q*4+2]+bv.z, a1[q*4+3]+bv.w);
    }
}

// ---------------------------------------------------------------------------
__global__ void bar_reset_kernel() {
    if (threadIdx.x < TT) { g_bar[threadIdx.x] = 0u; g_task[threadIdx.x] = 0u; }
}

// ---------------------------------------------------------------------------
// Kernel 2: persistent LSTM, dynamic task queue for load balance.
// grid 592 (4 CTA/SM resident), 128 threads. Task = 32x8 px x 32 gates.
// ---------------------------------------------------------------------------
__global__ void __launch_bounds__(128, 4) lstm_persistent(
    const float* __restrict__ Wh,
    const float* __restrict__ gamma, const float* __restrict__ beta,
    const float* __restrict__ mmean, const float* __restrict__ mvar,
    float* __restrict__ out)
{
    extern __shared__ float sm[];
    float* s_in = sm;
    float* s_w  = sm + LSIN_FLOATS;
    unsigned* s_task = (unsigned*)(sm + LSIN_FLOATS + SWBUF_FLOATS);

    const int tid = threadIdx.x;
    const int px = tid & 31, pr = tid >> 5;      // pr in 0..3

    for (int t = 0; t < TT; t++) {
        for (;;) {
            if (tid == 0) s_task[0] = atomicAdd(&g_task[t], 1u);
            __syncthreads();                      // broadcast + smem reuse fence
            const unsigned task = s_task[0];
            if (task >= NTASKS) break;

            // decode: b(3) | fc(2) | tile(4)
            const int tile = task & 15;
            const int fc   = (task >> 4) & 3;
            const int bb   = task >> 6;
            const int tx0 = (tile & 1) * TW;
            const int ty0 = (tile >> 1) * LTH;

            unsigned long long acc0[16], acc1[16];
#pragma unroll
            for (int m = 0; m < 16; m++) { acc0[m] = 0ull; acc1[m] = 0ull; }

            if (t > 0) {
                const float* hin = g_h[(t + 1) & 1] + (size_t)bb * FF * HH * WW;
                load_h_tile10(s_in, hin, ty0, tx0, tid);
                load_tap_lstm128(s_w, Wh, 0, fc, tid);
                __syncthreads();
#pragma unroll
                for (int tap = 0; tap < 9; tap++) {
                    if (tap < 8)
                        load_tap_lstm128(&s_w[((tap + 1) & 1) * 1024], Wh,
                                         tap + 1, fc, tid);
                    conv_tap_t<4>(s_in, &s_w[(tap & 1) * 1024], pr, px,
                                  tap / 3, tap % 3, acc0, acc1);
                    __syncthreads();
                }
            }

            float a0[32], a1[32];
#pragma unroll
            for (int m = 0; m < 16; m++) {
                unpack2(acc0[m], a0[2 * m], a0[2 * m + 1]);
                unpack2(acc1[m], a1[2 * m], a1[2 * m + 1]);
            }

            // BN constants for this fc (cheap vs task compute)
            float inv[8], off[8];
#pragma unroll
            for (int j = 0; j < 8; j++) {
                int f = fc * 8 + j;
                inv[j] = gamma[f] * rsqrtf(mvar[f] + BN_EPS);
                off[j] = beta[f] - mmean[f] * inv[j];
            }

            float* hbase = g_h[t & 1] + (size_t)bb * FF * HH * WW;
            const int gx = tx0 + px;

#pragma unroll
            for (int p = 0; p < 2; p++) {
                const float* a = p ? a1 : a0;
                const int gy = ty0 + pr + p * 4;
                const size_t pix   = (size_t)bb * HH * WW + (size_t)gy * WW + gx;
                const size_t frame = (size_t)(bb * TT + t) * HH * WW
                                     + (size_t)gy * WW + gx;
                const float* xgp = &g_xg[frame * G4F];
                float* cst = &g_c[pix * FF + fc * 8];
                float* op  = &out[frame * FF + fc * 8];

                float coldv[8] = {0,0,0,0,0,0,0,0};
                if (t > 0) {
                    float4 c0 = ((const float4*)cst)[0];
                    float4 c1 = ((const float4*)cst)[1];
                    coldv[0]=c0.x; coldv[1]=c0.y; coldv[2]=c0.z; coldv[3]=c0.w;
                    coldv[4]=c1.x; coldv[5]=c1.y; coldv[6]=c1.z; coldv[7]=c1.w;
                }

                float cv[8], hv[8], ov[8];
#pragma unroll
                for (int j = 0; j < 8; j++) {
                    int f = fc * 8 + j;
                    float gi = a[0 * 8 + j] + __ldg(&xgp[0 * 32 + f]);
                    float gf = a[1 * 8 + j] + __ldg(&xgp[1 * 32 + f]);
                    float gc = a[2 * 8 + j] + __ldg(&xgp[2 * 32 + f]);
                    float go = a[3 * 8 + j] + __ldg(&xgp[3 * 32 + f]);
                    gi = hsig(gi); gf = hsig(gf); go = hsig(go);
                    float cn = gf * coldv[j] + gi * tanhf(gc);
                    float h  = go * tanhf(cn);
                    cv[j] = cn; hv[j] = h;
                    ov[j] = fmaf(h, inv[j], off[j]);
                }
                ((float4*)cst)[0] = make_float4(cv[0], cv[1], cv[2], cv[3]);
                ((float4*)cst)[1] = make_float4(cv[4], cv[5], cv[6], cv[7]);
#pragma unroll
                for (int j = 0; j < 8; j++) {
                    int f = fc * 8 + j;
                    hbase[((size_t)f * HH + gy) * WW + gx] = hv[j];
                }
                ((float4*)op)[0] = make_float4(ov[0], ov[1], ov[2], ov[3]);
                ((float4*)op)[1] = make_float4(ov[4], ov[5], ov[6], ov[7]);
            }
        }

        // step barrier: all 592 CTAs; publishes h_t for step t+1
        if (t < TT - 1) {
            __threadfence();
            __syncthreads();
            if (tid == 0) {
                atomicAdd(&g_bar[t], 1u);
                while (*((volatile unsigned*)&g_bar[t]) < (unsigned)LSTM_GRID)
                    __nanosleep(64);
            }
            __syncthreads();
            __threadfence();
        }
    }
}

// ===========================================================================
extern "C" void kernel_launch(void* const* d_in, const int* in_sizes, int n_in,
                              void* d_out, int out_size)
{
    const float* x     = (const float*)d_in[0];
    const float* Wx    = (const float*)d_in[1];
    const float* Wh    = (const float*)d_in[2];
    const float* b     = (const float*)d_in[3];
    const float* gamma = (const float*)d_in[4];
    const float* beta  = (const float*)d_in[5];
    const float* mmean = (const float*)d_in[6];
    const float* mvar  = (const float*)d_in[7];
    float* out = (float*)d_out;

    cudaFuncSetAttribute(xg_conv_kernel,
        cudaFuncAttributeMaxDynamicSharedMemorySize, XG_SMEM);
    cudaFuncSetAttribute(lstm_persistent,
        cudaFuncAttributeMaxDynamicSharedMemorySize, LS_SMEM);

    // 1) input-to-gate conv (R10 config, measured 805us)
    {
        dim3 grid(8, 4, BB * TT);
        xg_conv_kernel<<<grid, 256, XG_SMEM>>>(x, Wx, b);
    }
    // 2) persistent recurrence: dynamic task queue, 4 CTA/SM balanced
    bar_reset_kernel<<<1, 32>>>();
    lstm_persistent<<<LSTM_GRID, 128, LS_SMEM>>>(
        Wh, gamma, beta, mmean, mvar, out);
}

// round 12
// speedup vs baseline: 1.0829x; 1.0829x over previous
#include <cuda_runtime.h>
#include <cuda_bf16.h>
#include <cstddef>

// Problem constants
#define BB 8
#define TT 16
#define HH 64
#define WW 64
#define CIN 32
#define FF 32
#define G4F 128
#define BN_EPS 1e-3f

typedef unsigned long long ull;

// ===================== xg kernel geometry (NEW: 32x32 tile, 4px/thread) ====
#define XTW 32
#define XTH 32
#define XIN_ROWS 34
#define XIN_COLS 34
#define XROW_STRIDE (32 * XIN_COLS)            // 1088 floats per smem row
#define XSIN_FLOATS (XIN_ROWS * XROW_STRIDE)   // 36992
#define XSW_FLOATS (9 * 32 * 32)               // 9216 (all taps staged)
#define XG_SMEM ((XSIN_FLOATS + XSW_FLOATS) * 4)   // 184832 B -> 1 CTA/SM

// ===================== lstm geometry (R10, measured 77us/step) =============
#define TW 32
#define TH 16
#define IN_ROWS 18
#define IN_COLS 34
#define ROW_STRIDE (32 * IN_COLS)
#define SIN_FLOATS (IN_ROWS * ROW_STRIDE)     // 19584
#define SWBUF_FLOATS (2 * 32 * 32)            // 2048
#define LS_SMEM ((SIN_FLOATS + SWBUF_FLOATS) * 4)  // 86528 -> 2 CTA/SM
#define LSTM_GRID 256

// ======================= device scratch (no allocs) ========================
__device__ float g_xg[(size_t)BB * TT * HH * WW * G4F];
// h state TRANSPOSED: [2][b][f][y][x]
__device__ float g_h[2][(size_t)BB * FF * HH * WW];
__device__ float g_c[(size_t)BB * HH * WW * FF];
__device__ unsigned g_bar[TT];

// ======================= helpers ===========================================
__device__ __forceinline__ float hsig(float x) {
    return __saturatef(fmaf(0.2f, x, 0.5f));
}
__device__ __forceinline__ ull pack2(float v) {
    ull r;
    asm("mov.b64 %0, {%1, %1};" : "=l"(r) : "f"(v));
    return r;
}
__device__ __forceinline__ void ffma2(ull& d, ull a, ull b) {
    asm("fma.rn.f32x2 %0, %1, %2, %3;" : "=l"(d) : "l"(a), "l"(b), "l"(d));
}
__device__ __forceinline__ void unpack2(ull p, float& lo, float& hi) {
    asm("mov.b64 {%0, %1}, %2;" : "=f"(lo), "=f"(hi) : "l"(p));
}

// ---------------------------------------------------------------------------
// Kernel 1: xg = conv(x, Wx) + b. NEW: 32x32 tile, 256 thr, 4 px/thread,
// all weights staged, ONE sync, crossbar demand ~37% of fma pipe.
// grid (4 tiles, 4 cout-chunks, 128 frames).
// ---------------------------------------------------------------------------
__global__ void __launch_bounds__(256, 1) xg_conv_kernel(
    const float* __restrict__ x, const float* __restrict__ Wx,
    const float* __restrict__ b)
{
    extern __shared__ float sm[];
    float* s_in = sm;                     // [34 rows][32 cin][34 cols]
    float* s_w  = sm + XSIN_FLOATS;       // [9 taps][32 cin][32 cout]

    const int tile = blockIdx.x;          // 0..3: 2x2 tiles of 32x32
    const int cc   = blockIdx.y;          // cout chunk 0..3
    const int n    = blockIdx.z;          // frame 0..127
    const int tx0 = (tile & 1) * XTW;
    const int ty0 = (tile >> 1) * XTH;
    const int tid = threadIdx.x;

    // stage input tile 34x34 x 32cin: LDG.128 along cin + scalar STS
    {
        const float* xin = x + (size_t)n * HH * WW * CIN;
        for (int j = tid; j < 1156 * 8; j += 256) {
            int c4 = j & 7;
            int p  = j >> 3;               // 0..1155
            int row = p / XIN_COLS, col = p - row * XIN_COLS;
            int gy = ty0 + row - 1, gx = tx0 + col - 1;
            float4 v = make_float4(0.f, 0.f, 0.f, 0.f);
            if ((unsigned)gy < (unsigned)HH && (unsigned)gx < (unsigned)WW)
                v = __ldg((const float4*)&xin[((size_t)gy * WW + gx) * CIN + c4 * 4]);
            float* d = &s_in[(row * 32 + c4 * 4) * XIN_COLS + col];
            d[0 * XIN_COLS] = v.x;
            d[1 * XIN_COLS] = v.y;
            d[2 * XIN_COLS] = v.z;
            d[3 * XIN_COLS] = v.w;
        }
    }
    // stage ALL 9 taps of this cout chunk: 9216 floats, 9 float4/thread
    for (int i = tid; i < 2304; i += 256) {
        int k = i >> 3, co4 = i & 7;       // k = tap*32+cin (0..287)
        float4 w = *(const float4*)&Wx[(size_t)k * G4F + cc * 32 + co4 * 4];
        *(float4*)&s_w[k * 32 + co4 * 4] = w;
    }
    __syncthreads();

    const int px = tid & 31, wid = tid >> 5;   // px = col, wid = row group
    ull aA[16], aB[16], aC[16], aD[16];
#pragma unroll
    for (int m = 0; m < 16; m++) { aA[m]=0ull; aB[m]=0ull; aC[m]=0ull; aD[m]=0ull; }

#pragma unroll
    for (int dy = 0; dy < 3; dy++) {
#pragma unroll
        for (int dx = 0; dx < 3; dx++) {
            const float* i0 = &s_in[(wid + dy) * XROW_STRIDE + (px + dx)];
            const float* i1 = i0 + 8  * XROW_STRIDE;
            const float* i2 = i0 + 16 * XROW_STRIDE;
            const float* i3 = i0 + 24 * XROW_STRIDE;
            const float* wb = &s_w[(dy * 3 + dx) * 1024];
#pragma unroll 2
            for (int cin = 0; cin < 32; cin++) {
                ull v0 = pack2(i0[cin * XIN_COLS]);
                ull v1 = pack2(i1[cin * XIN_COLS]);
                ull v2 = pack2(i2[cin * XIN_COLS]);
                ull v3 = pack2(i3[cin * XIN_COLS]);
                const ulonglong2* w2 = (const ulonglong2*)(wb + cin * 32);
#pragma unroll
                for (int q = 0; q < 8; q++) {
                    ulonglong2 w = w2[q];
                    ffma2(aA[q*2+0], v0, w.x); ffma2(aA[q*2+1], v0, w.y);
                    ffma2(aB[q*2+0], v1, w.x); ffma2(aB[q*2+1], v1, w.y);
                    ffma2(aC[q*2+0], v2, w.x); ffma2(aC[q*2+1], v2, w.y);
                    ffma2(aD[q*2+0], v3, w.x); ffma2(aD[q*2+1], v3, w.y);
                }
            }
        }
    }

    // epilogue: per row group, unpack + bias + store
    const int gx = tx0 + px;
#pragma unroll
    for (int r = 0; r < 4; r++) {
        const ull* a = (r == 0) ? aA : (r == 1) ? aB : (r == 2) ? aC : aD;
        float v[32];
#pragma unroll
        for (int m = 0; m < 16; m++) unpack2(a[m], v[2*m], v[2*m+1]);
        const int gy = ty0 + wid + r * 8;
        float* op = &g_xg[(((size_t)n * HH + gy) * WW + gx) * G4F + cc * 32];
#pragma unroll
        for (int q = 0; q < 8; q++) {
            float4 bv = *(const float4*)&b[cc * 32 + q * 4];
            ((float4*)op)[q] = make_float4(v[q*4+0]+bv.x, v[q*4+1]+bv.y,
                                           v[q*4+2]+bv.z, v[q*4+3]+bv.w);
        }
    }
}

// ===========================================================================
// LSTM side: R10 verbatim (persistent, tap-streamed, transposed h, 77us/step)
// ===========================================================================
__device__ __forceinline__ void conv_tap(
    const float* __restrict__ s_in, const float* __restrict__ wb,
    int pr, int px, int dy, int dx, ull* acc0, ull* acc1)
{
    const float* i0 = &s_in[(pr + dy) * ROW_STRIDE + (px + dx)];
    const float* i1 = i0 + 8 * ROW_STRIDE;
#pragma unroll 4
    for (int cin = 0; cin < 32; cin++) {
        ull v0 = pack2(i0[cin * IN_COLS]);
        ull v1 = pack2(i1[cin * IN_COLS]);
        const ulonglong2* w2 = (const ulonglong2*)(wb + cin * 32);
#pragma unroll
        for (int q = 0; q < 8; q++) {
            ulonglong2 w = w2[q];
            ffma2(acc0[q * 2 + 0], v0, w.x);
            ffma2(acc0[q * 2 + 1], v0, w.y);
            ffma2(acc1[q * 2 + 0], v1, w.x);
            ffma2(acc1[q * 2 + 1], v1, w.y);
        }
    }
}

__device__ __forceinline__ void load_tap_lstm(
    float* __restrict__ dst, const float* __restrict__ Wh, int kk, int fc, int tid)
{
    int cin = tid >> 3, col0 = (tid & 7) * 4;
    int cout0 = (col0 >> 3) * 32 + fc * 8 + (col0 & 7);
    float4 w = *(const float4*)&Wh[((size_t)(kk * CIN + cin)) * G4F + cout0];
    *(float4*)&dst[cin * 32 + col0] = w;
}

__device__ __forceinline__ void load_h_tile(
    float* __restrict__ s_in, const float* __restrict__ src,
    int ty0, int tx0, int tid)
{
    for (int j = tid; j < 18 * 32 * 8; j += 256) {
        int c4  = j & 7;
        int cin = (j >> 3) & 31;
        int row = j >> 8;
        int gy = ty0 + row - 1;
        int gx0 = tx0 + c4 * 4;
        float4 v = make_float4(0.f, 0.f, 0.f, 0.f);
        if ((unsigned)gy < (unsigned)HH)
            v = __ldcv((const float4*)&src[((size_t)cin * HH + gy) * WW + gx0]);
        float* d = &s_in[(row * 32 + cin) * IN_COLS + (c4 * 4 + 1)];
        d[0] = v.x; d[1] = v.y; d[2] = v.z; d[3] = v.w;
    }
    for (int j = tid; j < 18 * 32 * 2; j += 256) {
        int e   = j & 1;
        int cin = (j >> 1) & 31;
        int row = j >> 6;
        int gy = ty0 + row - 1;
        int gx = e ? (tx0 + 32) : (tx0 - 1);
        float v = 0.f;
        if ((unsigned)gy < (unsigned)HH && (unsigned)gx < (unsigned)WW)
            v = __ldcv(&src[((size_t)cin * HH + gy) * WW + gx]);
        s_in[(row * 32 + cin) * IN_COLS + (e ? 33 : 0)] = v;
    }
}

__global__ void bar_reset_kernel() {
    if (threadIdx.x < TT) g_bar[threadIdx.x] = 0u;
}

__global__ void __launch_bounds__(256, 2) lstm_persistent(
    const float* __restrict__ Wh,
    const float* __restrict__ gamma, const float* __restrict__ beta,
    const float* __restrict__ mmean, const float* __restrict__ mvar,
    float* __restrict__ out)
{
    extern __shared__ float sm[];
    float* s_in = sm;
    float* s_w  = sm + SIN_FLOATS;

    const int cta  = blockIdx.x;
    const int tile = cta & 7;
    const int fc   = (cta >> 3) & 3;
    const int bb   = cta >> 5;
    const int tx0 = (tile & 1) * TW;
    const int ty0 = (tile >> 1) * TH;
    const int tid = threadIdx.x;
    const int px = tid & 31, pr = tid >> 5;
    const int gx = tx0 + px;
    const int gy0 = ty0 + pr;

    float inv[8], off[8];
#pragma unroll
    for (int j = 0; j < 8; j++) {
        int f = fc * 8 + j;
        inv[j] = gamma[f] * rsqrtf(mvar[f] + BN_EPS);
        off[j] = beta[f] - mmean[f] * inv[j];
    }

    for (int t = 0; t < TT; t++) {
        ull acc0[16], acc1[16];
#pragma unroll
        for (int m = 0; m < 16; m++) { acc0[m] = 0ull; acc1[m] = 0ull; }

        if (t > 0) {
            const float* hin = g_h[(t + 1) & 1] + (size_t)bb * FF * HH * WW;
            load_h_tile(s_in, hin, ty0, tx0, tid);
            load_tap_lstm(s_w, Wh, 0, fc, tid);
            __syncthreads();
#pragma unroll
            for (int tap = 0; tap < 9; tap++) {
                if (tap < 8)
                    load_tap_lstm(&s_w[((tap + 1) & 1) * 1024], Wh, tap + 1, fc, tid);
                conv_tap(s_in, &s_w[(tap & 1) * 1024], pr, px, tap / 3, tap % 3,
                         acc0, acc1);
                __syncthreads();
            }
        }

        float a0[32], a1[32];
#pragma unroll
        for (int m = 0; m < 16; m++) {
            unpack2(acc0[m], a0[2 * m], a0[2 * m + 1]);
            unpack2(acc1[m], a1[2 * m], a1[2 * m + 1]);
        }

        float* hbase = g_h[t & 1] + (size_t)bb * FF * HH * WW;

#pragma unroll
        for (int p = 0; p < 2; p++) {
            const float* a = p ? a1 : a0;
            const int gy = gy0 + p * 8;
            const size_t pix   = (size_t)bb * HH * WW + (size_t)gy * WW + gx;
            const size_t frame = (size_t)(bb * TT + t) * HH * WW + (size_t)gy * WW + gx;
            const float* xgp = &g_xg[frame * G4F];
            float* cst = &g_c[pix * FF + fc * 8];
            float* op  = &out[frame * FF + fc * 8];

            float coldv[8] = {0,0,0,0,0,0,0,0};
            if (t > 0) {
                float4 c0 = ((const float4*)cst)[0];
                float4 c1 = ((const float4*)cst)[1];
                coldv[0]=c0.x; coldv[1]=c0.y; coldv[2]=c0.z; coldv[3]=c0.w;
                coldv[4]=c1.x; coldv[5]=c1.y; coldv[6]=c1.z; coldv[7]=c1.w;
            }

            float cv[8], hv[8], ov[8];
#pragma unroll
            for (int j = 0; j < 8; j++) {
                int f = fc * 8 + j;
                float gi = a[0 * 8 + j] + __ldg(&xgp[0 * 32 + f]);
                float gf = a[1 * 8 + j] + __ldg(&xgp[1 * 32 + f]);
                float gc = a[2 * 8 + j] + __ldg(&xgp[2 * 32 + f]);
                float go = a[3 * 8 + j] + __ldg(&xgp[3 * 32 + f]);
                gi = hsig(gi); gf = hsig(gf); go = hsig(go);
                float cn = gf * coldv[j] + gi * tanhf(gc);
                float h  = go * tanhf(cn);
                cv[j] = cn; hv[j] = h;
                ov[j] = fmaf(h, inv[j], off[j]);
            }
            ((float4*)cst)[0] = make_float4(cv[0], cv[1], cv[2], cv[3]);
            ((float4*)cst)[1] = make_float4(cv[4], cv[5], cv[6], cv[7]);
#pragma unroll
            for (int j = 0; j < 8; j++) {
                int f = fc * 8 + j;
                hbase[((size_t)f * HH + gy) * WW + gx] = hv[j];
            }
            ((float4*)op)[0] = make_float4(ov[0], ov[1], ov[2], ov[3]);
            ((float4*)op)[1] = make_float4(ov[4], ov[5], ov[6], ov[7]);
        }

        if (t < TT - 1) {
            __threadfence();
            __syncthreads();
            if (tid == 0) {
                atomicAdd(&g_bar[t], 1u);
                while (*((volatile unsigned*)&g_bar[t]) < (unsigned)LSTM_GRID)
                    __nanosleep(64);
            }
            __syncthreads();
            __threadfence();
        }
    }
}

// ===========================================================================
extern "C" void kernel_launch(void* const* d_in, const int* in_sizes, int n_in,
                              void* d_out, int out_size)
{
    const float* x     = (const float*)d_in[0];
    const float* Wx    = (const float*)d_in[1];
    const float* Wh    = (const float*)d_in[2];
    const float* b     = (const float*)d_in[3];
    const float* gamma = (const float*)d_in[4];
    const float* beta  = (const float*)d_in[5];
    const float* mmean = (const float*)d_in[6];
    const float* mvar  = (const float*)d_in[7];
    float* out = (float*)d_out;

    cudaFuncSetAttribute(xg_conv_kernel,
        cudaFuncAttributeMaxDynamicSharedMemorySize, XG_SMEM);
    cudaFuncSetAttribute(lstm_persistent,
        cudaFuncAttributeMaxDynamicSharedMemorySize, LS_SMEM);

    // 1) input-to-gate conv: 4px/thread, single-sync, crossbar-relieved
    {
        dim3 grid(4, 4, BB * TT);
        xg_conv_kernel<<<grid, 256, XG_SMEM>>>(x, Wx, b);
    }
    // 2) persistent recurrence (R10 verbatim)
    bar_reset_kernel<<<1, 32>>>();
    lstm_persistent<<<LSTM_GRID, 256, LS_SMEM>>>(
        Wh, gamma, beta, mmean, mvar, out);
}

// round 13
// speedup vs baseline: 1.2895x; 1.1908x over previous
#include <cuda_runtime.h>
#include <cuda_bf16.h>
#include <cstddef>

// Problem constants
#define BB 8
#define TT 16
#define HH 64
#define WW 64
#define CIN 32
#define FF 32
#define G4F 128
#define BN_EPS 1e-3f

typedef unsigned long long ull;

// ===== geometry: 32x16 tile, 256 threads, 2 px/thread (rows pr, pr+8) =====
#define TW 32
#define TH 16
#define IN_ROWS 18
#define IN_COLS 34
#define ROW_STRIDE (32 * IN_COLS)
#define SIN_FLOATS (IN_ROWS * ROW_STRIDE)     // 19584
#define SWBUF_FLOATS (2 * 32 * 32)            // 2048 (double-buffered tap)
#define SBIAS_FLOATS 32
#define LS_SMEM ((SIN_FLOATS + SWBUF_FLOATS + SBIAS_FLOATS) * 4)  // 86656 -> 2 CTA/SM
#define LSTM_GRID 256

// ======================= device scratch (no allocs) ========================
// h state TRANSPOSED: [2][b][f][y][x]
__device__ float g_h[2][(size_t)BB * FF * HH * WW];
__device__ float g_c[(size_t)BB * HH * WW * FF];
__device__ unsigned g_bar[TT];

// ======================= helpers ===========================================
__device__ __forceinline__ float hsig(float x) {
    return __saturatef(fmaf(0.2f, x, 0.5f));
}
__device__ __forceinline__ ull pack2(float v) {
    ull r;
    asm("mov.b64 %0, {%1, %1};" : "=l"(r) : "f"(v));
    return r;
}
__device__ __forceinline__ void ffma2(ull& d, ull a, ull b) {
    asm("fma.rn.f32x2 %0, %1, %2, %3;" : "=l"(d) : "l"(a), "l"(b), "l"(d));
}
__device__ __forceinline__ void unpack2(ull p, float& lo, float& hi) {
    asm("mov.b64 {%0, %1}, %2;" : "=f"(lo), "=f"(hi) : "l"(p));
}

// One 3x3 tap (dy,dx) over 32 cin for 2 pixels, 32 couts. (proven core)
__device__ __forceinline__ void conv_tap(
    const float* __restrict__ s_in, const float* __restrict__ wb,
    int pr, int px, int dy, int dx, ull* acc0, ull* acc1)
{
    const float* i0 = &s_in[(pr + dy) * ROW_STRIDE + (px + dx)];
    const float* i1 = i0 + 8 * ROW_STRIDE;
#pragma unroll 4
    for (int cin = 0; cin < 32; cin++) {
        ull v0 = pack2(i0[cin * IN_COLS]);
        ull v1 = pack2(i1[cin * IN_COLS]);
        const ulonglong2* w2 = (const ulonglong2*)(wb + cin * 32);
#pragma unroll
        for (int q = 0; q < 8; q++) {
            ulonglong2 w = w2[q];
            ffma2(acc0[q * 2 + 0], v0, w.x);
            ffma2(acc0[q * 2 + 1], v0, w.y);
            ffma2(acc1[q * 2 + 0], v1, w.x);
            ffma2(acc1[q * 2 + 1], v1, w.y);
        }
    }
}

// Gate-interleaved tap loader (works for Wx and Wh; both [tap*32+cin][G4F]):
// smem col = g*8+j  ->  gmem cout = g*32 + fc*8 + j
__device__ __forceinline__ void load_tap_w(
    float* __restrict__ dst, const float* __restrict__ W, int kk, int fc, int tid)
{
    int cin = tid >> 3, col0 = (tid & 7) * 4;
    int cout0 = (col0 >> 3) * 32 + fc * 8 + (col0 & 7);
    float4 w = *(const float4*)&W[((size_t)(kk * CIN + cin)) * G4F + cout0];
    *(float4*)&dst[cin * 32 + col0] = w;
}

// x tile loader: [y][x][cin] gmem (NHWC), float4 along cin.
__device__ __forceinline__ void load_x_tile(
    float* __restrict__ s_in, const float* __restrict__ src,
    int ty0, int tx0, int tid)
{
    for (int j = tid; j < 612 * 8; j += 256) {
        int c4 = j & 7;
        int p  = j >> 3;
        int row = p / IN_COLS, col = p - row * IN_COLS;
        int gy = ty0 + row - 1, gx = tx0 + col - 1;
        float4 v = make_float4(0.f, 0.f, 0.f, 0.f);
        if ((unsigned)gy < (unsigned)HH && (unsigned)gx < (unsigned)WW)
            v = __ldg((const float4*)&src[((size_t)gy * WW + gx) * CIN + c4 * 4]);
        float* d = &s_in[(row * 32 + c4 * 4) * IN_COLS + col];
        d[0 * IN_COLS] = v.x;
        d[1 * IN_COLS] = v.y;
        d[2 * IN_COLS] = v.z;
        d[3 * IN_COLS] = v.w;
    }
}

// h tile loader from TRANSPOSED layout [f][y][x]: L1-bypassing float4 loads.
__device__ __forceinline__ void load_h_tile(
    float* __restrict__ s_in, const float* __restrict__ src,
    int ty0, int tx0, int tid)
{
    for (int j = tid; j < 18 * 32 * 8; j += 256) {
        int c4  = j & 7;
        int cin = (j >> 3) & 31;
        int row = j >> 8;
        int gy = ty0 + row - 1;
        int gx0 = tx0 + c4 * 4;
        float4 v = make_float4(0.f, 0.f, 0.f, 0.f);
        if ((unsigned)gy < (unsigned)HH)
            v = __ldcv((const float4*)&src[((size_t)cin * HH + gy) * WW + gx0]);
        float* d = &s_in[(row * 32 + cin) * IN_COLS + (c4 * 4 + 1)];
        d[0] = v.x; d[1] = v.y; d[2] = v.z; d[3] = v.w;
    }
    for (int j = tid; j < 18 * 32 * 2; j += 256) {
        int e   = j & 1;
        int cin = (j >> 1) & 31;
        int row = j >> 6;
        int gy = ty0 + row - 1;
        int gx = e ? (tx0 + 32) : (tx0 - 1);
        float v = 0.f;
        if ((unsigned)gy < (unsigned)HH && (unsigned)gx < (unsigned)WW)
            v = __ldcv(&src[((size_t)cin * HH + gy) * WW + gx]);
        s_in[(row * 32 + cin) * IN_COLS + (e ? 33 : 0)] = v;
    }
}

__global__ void bar_reset_kernel() {
    if (threadIdx.x < TT) g_bar[threadIdx.x] = 0u;
}

// ---------------------------------------------------------------------------
// THE kernel: fully fused persistent ConvLSTM.
// Per step: g = conv(x_t, Wx) + conv(h_{t-1}, Wh) + b   (both convs fused
// into the same f32x2 accumulators, bias folded into acc init), then gates,
// c/h update, BatchNorm, output store. No xg scratch round-trip at all.
// grid 256 CTAs (2/SM co-resident), block 256, 2 px/thread.
// ---------------------------------------------------------------------------
__global__ void __launch_bounds__(256, 2) convlstm_persistent(
    const float* __restrict__ x, const float* __restrict__ Wx,
    const float* __restrict__ Wh, const float* __restrict__ b,
    const float* __restrict__ gamma, const float* __restrict__ beta,
    const float* __restrict__ mmean, const float* __restrict__ mvar,
    float* __restrict__ out)
{
    extern __shared__ float sm[];
    float* s_in   = sm;
    float* s_w    = sm + SIN_FLOATS;
    float* s_bias = sm + SIN_FLOATS + SWBUF_FLOATS;

    const int cta  = blockIdx.x;
    const int tile = cta & 7;
    const int fc   = (cta >> 3) & 3;
    const int bb   = cta >> 5;
    const int tx0 = (tile & 1) * TW;
    const int ty0 = (tile >> 1) * TH;
    const int tid = threadIdx.x;
    const int px = tid & 31, pr = tid >> 5;
    const int gx = tx0 + px;
    const int gy0 = ty0 + pr;

    // BN constants (loop-invariant)
    float inv[8], off[8];
#pragma unroll
    for (int j = 0; j < 8; j++) {
        int f = fc * 8 + j;
        inv[j] = gamma[f] * rsqrtf(mvar[f] + BN_EPS);
        off[j] = beta[f] - mmean[f] * inv[j];
    }
    // interleaved bias into smem: s_bias[col] = b[(col>>3)*32 + fc*8 + (col&7)]
    if (tid < 32)
        s_bias[tid] = b[(tid >> 3) * 32 + fc * 8 + (tid & 7)];
    __syncthreads();

    for (int t = 0; t < TT; t++) {
        // init accumulators with bias (packed pairs from smem)
        ull acc0[16], acc1[16];
#pragma unroll
        for (int m = 0; m < 16; m++) {
            ull bv = *(const ull*)&s_bias[2 * m];
            acc0[m] = bv; acc1[m] = bv;
        }

        // ---- x contribution: conv(x_t, Wx) ----
        load_x_tile(s_in, x + (size_t)(bb * TT + t) * HH * WW * CIN, ty0, tx0, tid);
        load_tap_w(s_w, Wx, 0, fc, tid);
        __syncthreads();
#pragma unroll
        for (int tap = 0; tap < 9; tap++) {
            if (tap < 8)
                load_tap_w(&s_w[((tap + 1) & 1) * 1024], Wx, tap + 1, fc, tid);
            conv_tap(s_in, &s_w[(tap & 1) * 1024], pr, px, tap / 3, tap % 3,
                     acc0, acc1);
            __syncthreads();
        }

        // ---- h contribution: conv(h_{t-1}, Wh) (reuses s_in post-sync) ----
        if (t > 0) {
            const float* hin = g_h[(t + 1) & 1] + (size_t)bb * FF * HH * WW;
            load_h_tile(s_in, hin, ty0, tx0, tid);
            load_tap_w(s_w, Wh, 0, fc, tid);
            __syncthreads();
#pragma unroll
            for (int tap = 0; tap < 9; tap++) {
                if (tap < 8)
                    load_tap_w(&s_w[((tap + 1) & 1) * 1024], Wh, tap + 1, fc, tid);
                conv_tap(s_in, &s_w[(tap & 1) * 1024], pr, px, tap / 3, tap % 3,
                         acc0, acc1);
                __syncthreads();
            }
        }

        // ---- epilogue: gates, c/h update, BN, stores ----
        float a0[32], a1[32];
#pragma unroll
        for (int m = 0; m < 16; m++) {
            unpack2(acc0[m], a0[2 * m], a0[2 * m + 1]);
            unpack2(acc1[m], a1[2 * m], a1[2 * m + 1]);
        }

        float* hbase = g_h[t & 1] + (size_t)bb * FF * HH * WW;

#pragma unroll
        for (int p = 0; p < 2; p++) {
            const float* a = p ? a1 : a0;
            const int gy = gy0 + p * 8;
            const size_t pix   = (size_t)bb * HH * WW + (size_t)gy * WW + gx;
            const size_t frame = (size_t)(bb * TT + t) * HH * WW + (size_t)gy * WW + gx;
            float* cst = &g_c[pix * FF + fc * 8];
            float* op  = &out[frame * FF + fc * 8];

            float coldv[8] = {0,0,0,0,0,0,0,0};
            if (t > 0) {
                float4 c0 = ((const float4*)cst)[0];
                float4 c1 = ((const float4*)cst)[1];
                coldv[0]=c0.x; coldv[1]=c0.y; coldv[2]=c0.z; coldv[3]=c0.w;
                coldv[4]=c1.x; coldv[5]=c1.y; coldv[6]=c1.z; coldv[7]=c1.w;
            }

            float cv[8], hv[8], ov[8];
#pragma unroll
            for (int j = 0; j < 8; j++) {
                float gi = hsig(a[0 * 8 + j]);
                float gf = hsig(a[1 * 8 + j]);
                float gc = a[2 * 8 + j];
                float go = hsig(a[3 * 8 + j]);
                float cn = gf * coldv[j] + gi * tanhf(gc);
                float h  = go * tanhf(cn);
                cv[j] = cn; hv[j] = h;
                ov[j] = fmaf(h, inv[j], off[j]);
            }
            ((float4*)cst)[0] = make_float4(cv[0], cv[1], cv[2], cv[3]);
            ((float4*)cst)[1] = make_float4(cv[4], cv[5], cv[6], cv[7]);
#pragma unroll
            for (int j = 0; j < 8; j++) {
                int f = fc * 8 + j;
                hbase[((size_t)f * HH + gy) * WW + gx] = hv[j];
            }
            ((float4*)op)[0] = make_float4(ov[0], ov[1], ov[2], ov[3]);
            ((float4*)op)[1] = make_float4(ov[4], ov[5], ov[6], ov[7]);
        }

        // grid barrier: publish h_t before step t+1
        if (t < TT - 1) {
            __threadfence();
            __syncthreads();
            if (tid == 0) {
                atomicAdd(&g_bar[t], 1u);
                while (*((volatile unsigned*)&g_bar[t]) < (unsigned)LSTM_GRID)
                    __nanosleep(64);
            }
            __syncthreads();
            __threadfence();
        }
    }
}

// ===========================================================================
extern "C" void kernel_launch(void* const* d_in, const int* in_sizes, int n_in,
                              void* d_out, int out_size)
{
    const float* x     = (const float*)d_in[0];
    const float* Wx    = (const float*)d_in[1];
    const float* Wh    = (const float*)d_in[2];
    const float* b     = (const float*)d_in[3];
    const float* gamma = (const float*)d_in[4];
    const float* beta  = (const float*)d_in[5];
    const float* mmean = (const float*)d_in[6];
    const float* mvar  = (const float*)d_in[7];
    float* out = (float*)d_out;

    cudaFuncSetAttribute(convlstm_persistent,
        cudaFuncAttributeMaxDynamicSharedMemorySize, LS_SMEM);

    bar_reset_kernel<<<1, 32>>>();
    convlstm_persistent<<<LSTM_GRID, 256, LS_SMEM>>>(
        x, Wx, Wh, b, gamma, beta, mmean, mvar, out);
}